// round 12
// baseline (speedup 1.0000x reference)
#include <cuda_runtime.h>

// FastECT: per-(batch,bin,theta) histogram + cumsum over bins.
// N=200000 pts (D=3), T=128 thetas, R=128 bins, B=64 batches, batch sorted.
//
// R12: barrier-free, stage-free; update path split across two HW mechanisms.
//  - Points read via direct warp-uniform float4 LDG (broadcast, L1-resident;
//    ~2.7KB per block). No smem staging, no tile barriers.
//  - Even points: plain u8 RMW into static HA (LSU ld/st path).
//    Odd points:  red.shared.add.u32 into static HB (smem atomic path).
//    Thread t owns theta t's words in both arrays -> race-free; the split
//    tests whether the two smem-update paths have independent throughput.
//  - u8, 4 bins/word/thread: word = (bin>>2)*128 + t -> bank t%32 for any
//    bin => conflict-free. Per-byte counts <= ~123 < 256 (exact).
//  - Flush reads ONLY the thread's own words (written only by itself) =>
//    no __syncthreads anywhere. Segment bounds computed redundantly and
//    uniformly per thread (8-step search in the block's narrow window).
// cumsum linear => flush cumsum(HA+HB) into d_out via f32 atomicAdd (exact).

#define TT 128
#define RR 128
#define NBLK 888     // 148 SMs * 6 resident, single balanced wave

typedef unsigned int       u32;
typedef unsigned char      u8;

// lower_bound over [lo, hi) -- window is small (<=block range)
__device__ __forceinline__ int lower_bound_range(const int* __restrict__ a,
                                                 int lo, int hi, int key) {
    while (lo < hi) {
        int mid = (lo + hi) >> 1;
        if (a[mid] < key) lo = mid + 1; else hi = mid;
    }
    return lo;
}

// bin = clip(floor(f), 0, 127) for f = 64*nh + 64  (== (nh+1)*64 exactly):
// cvt.rzi.u32 saturates negatives to 0, floors positives; then min(.,127).
__device__ __forceinline__ u32 bin_of(float x0, float x1, float x2,
                                      float v0, float v1, float v2) {
    float nh = fmaf(x2, v2, fmaf(x1, v1, __fmul_rn(x0, v0)));
    float f  = fmaf(nh, 64.0f, 64.0f);
    return min(__float2uint_rz(f), 127u);
}

// fire-and-forget smem add (ATOMS.ADD no-return)
__device__ __forceinline__ void reds_add(u32 smem_addr, u32 val) {
    asm volatile("red.shared.add.u32 [%0], %1;" :: "r"(smem_addr), "r"(val) : "memory");
}

__global__ void __launch_bounds__(256)
k_zero(float* __restrict__ out, int n4) {
    int i = blockIdx.x * blockDim.x + threadIdx.x;
    if (i < n4) ((float4*)out)[i] = make_float4(0.f, 0.f, 0.f, 0.f);
}

__global__ void __launch_bounds__(128, 6)
k_hist(const float* __restrict__ x, const float* __restrict__ v,
       const int* __restrict__ batch, int n, float* __restrict__ out) {
    __shared__ u8 HA[RR * TT];                   // RMW path (even points)
    __shared__ u8 HB[RR * TT];                   // ATOMS path (odd points)

    const int t = threadIdx.x;
    const int g = blockIdx.x;

    u8* __restrict__ hA = HA + (t << 2);
    const u32 hBaddr = (u32)__cvta_generic_to_shared(HB) + ((u32)t << 2);

    const int lo = (int)(((long long)g)     * n / NBLK);
    const int hi = (int)(((long long)g + 1) * n / NBLK);

    const float v0 = v[t];
    const float v1 = v[TT + t];
    const float v2 = v[2 * TT + t];

    // zero own words only (thread-exclusive -> no barrier needed)
    {
        u32* wa = (u32*)HA;
        u32* wb = (u32*)HB;
#pragma unroll
        for (int w = 0; w < RR / 4; ++w) {
            wa[w * 128 + t] = 0u;
            wb[w * 128 + t] = 0u;
        }
    }

    const float4* __restrict__ x4 = (const float4*)x;

    int pos = lo;
    while (pos < hi) {
        const int b = batch[pos];                // uniform LDG broadcast
        const int seg_end = lower_bound_range(batch, pos, hi, b + 1);

        // head: scalar until pos is 4-point aligned (x4 index = pos/4*3)
        while (pos < seg_end && (pos & 3)) {
            u32 bn = bin_of(x[3 * pos], x[3 * pos + 1], x[3 * pos + 2], v0, v1, v2);
            u8* a = hA + ((bn >> 2) << 9) + (bn & 3);
            *a = (u8)(*a + 1);
            ++pos;
        }

        // main: 8 points per iter via 6 uniform float4 LDGs
        for (; pos + 8 <= seg_end; pos += 8) {
            const int qi = (pos >> 2) * 3;
            float4 q[6];
#pragma unroll
            for (int j = 0; j < 6; ++j) q[j] = x4[qi + j];
            const float* f = (const float*)q;    // f[3i+c] = comp c of pt i
            u32 bn[8];
#pragma unroll
            for (int i = 0; i < 8; ++i)
                bn[i] = bin_of(f[3 * i], f[3 * i + 1], f[3 * i + 2], v0, v1, v2);
#pragma unroll
            for (int i = 0; i < 8; i += 2) {
                // even -> RMW path
                u8* a = hA + ((bn[i] >> 2) << 9) + (bn[i] & 3);
                *a = (u8)(*a + 1);
                // odd -> smem-atomic path (no return, no dependency)
                reds_add(hBaddr + ((bn[i + 1] >> 2) << 9),
                         1u << ((bn[i + 1] & 3u) << 3));
            }
        }

        // tail: scalar
        for (; pos < seg_end; ++pos) {
            u32 bn = bin_of(x[3 * pos], x[3 * pos + 1], x[3 * pos + 2], v0, v1, v2);
            u8* a = hA + ((bn >> 2) << 9) + (bn & 3);
            *a = (u8)(*a + 1);
        }

        // flush: cumsum(HA+HB own words) += out[b][bin][t]; no barrier --
        // every word read here was written only by this thread (same-thread
        // same-address ordering covers the red.shared ops).
        {
            int acc = 0;
            u32* wa = (u32*)HA;
            u32* wb = (u32*)HB;
            float* dst = out + ((size_t)b * RR) * TT + t;
#pragma unroll
            for (int bin4 = 0; bin4 < RR / 4; ++bin4) {
                u32 a = wa[bin4 * 128 + t];
                u32 c = wb[bin4 * 128 + t];
                wa[bin4 * 128 + t] = 0u;         // rezero for next segment
                wb[bin4 * 128 + t] = 0u;
                acc += (int)(a & 255u) + (int)(c & 255u);
                atomicAdd(dst + (bin4 * 4 + 0) * TT, (float)acc);
                acc += (int)((a >> 8) & 255u) + (int)((c >> 8) & 255u);
                atomicAdd(dst + (bin4 * 4 + 1) * TT, (float)acc);
                acc += (int)((a >> 16) & 255u) + (int)((c >> 16) & 255u);
                atomicAdd(dst + (bin4 * 4 + 2) * TT, (float)acc);
                acc += (int)(a >> 24) + (int)(c >> 24);
                atomicAdd(dst + (bin4 * 4 + 3) * TT, (float)acc);
            }
        }
    }
}

extern "C" void kernel_launch(void* const* d_in, const int* in_sizes, int n_in,
                              void* d_out, int out_size) {
    const float* x     = (const float*)d_in[0];   // [200000, 3]
    const float* v     = (const float*)d_in[1];   // [3, 128]
    const int*   batch = (const int*)d_in[2];     // [200000], sorted
    const int n = in_sizes[2];

    float* out = (float*)d_out;                   // [64, 128, 128]
    const int n4 = out_size / 4;

    k_zero<<<(n4 + 255) / 256, 256>>>(out, n4);
    k_hist<<<NBLK, 128>>>(x, v, batch, n, out);
}

// round 13
// speedup vs baseline: 1.0413x; 1.0413x over previous
#include <cuda_runtime.h>

// FastECT: per-(batch,bin,theta) histogram + cumsum over bins.
// N=200000 pts (D=3), T=128 thetas, R=128 bins, B=64 batches, batch sorted.
//
// R13 = R11 hot loop (stage SoA + f32x2 + red.shared u8x4 updates) with a
// VECTORIZED flush. Model: one LSU/MIO queue @ ~4.3cyc/warp-op binds; flush
// was ~35% of all MIO ops. New flush, per thread:
//   8x LDS.128  (16 counts each: thetas 4l..4l+3 x 4 bins -- words already
//               adjacent in the hist layout) instead of 32x LDS.32
//   8x STS.128  rezero                        instead of 32x STS.32
//   32x red.global.add.v4.f32 (4 thetas/bin)  instead of 128x REDG.32
// Flush ownership transposes: warp w <-> bins [32w,32w+32), lane l <-> theta
// quad 4l..4l+3; chunk cumsum handoff via 2KB smem exchange + barrier.
// All counts integer-valued f32 => exact, deterministic.

#define TT 128
#define RR 128
#define NBLK 888     // 148 SMs * 6 resident, single balanced wave
#define TILE 256     // points staged per tile (SoA)

typedef unsigned int       u32;
typedef unsigned char      u8;
typedef unsigned long long u64;

__device__ __forceinline__ int lower_bound_i32(const int* __restrict__ a, int n, int key) {
    int lo = 0, hi = n;
    while (lo < hi) {
        int mid = (lo + hi) >> 1;
        if (a[mid] < key) lo = mid + 1; else hi = mid;
    }
    return lo;
}

// packed f32x2 helpers (sm_103a): same per-lane rounding as scalar chain
__device__ __forceinline__ u64 pack2(float lo, float hi) {
    u64 r; asm("mov.b64 %0, {%1, %2};" : "=l"(r) : "f"(lo), "f"(hi)); return r;
}
__device__ __forceinline__ void unpack2(u64 v, float& lo, float& hi) {
    asm("mov.b64 {%0, %1}, %2;" : "=f"(lo), "=f"(hi) : "l"(v));
}
__device__ __forceinline__ u64 mul2(u64 a, u64 b) {
    u64 r; asm("mul.rn.f32x2 %0, %1, %2;" : "=l"(r) : "l"(a), "l"(b)); return r;
}
__device__ __forceinline__ u64 fma2(u64 a, u64 b, u64 c) {
    u64 r; asm("fma.rn.f32x2 %0, %1, %2, %3;" : "=l"(r) : "l"(a), "l"(b), "l"(c)); return r;
}

// bin = clip(floor(f), 0, 127) for f = 64*nh + 64 (== (nh+1)*64 exactly)
__device__ __forceinline__ u32 bin_clamp(float f) {
    return min(__float2uint_rz(f), 127u);
}

// fire-and-forget smem add (ATOMS.ADD no-return)
__device__ __forceinline__ void reds_add(u32 smem_addr, u32 val) {
    asm volatile("red.shared.add.u32 [%0], %1;" :: "r"(smem_addr), "r"(val) : "memory");
}

// vector f32x4 global reduction (sm_90+), addr must be 16B aligned
__device__ __forceinline__ void redg_v4_f32(float* gaddr, float4 v) {
    asm volatile("red.global.add.v4.f32 [%0], {%1, %2, %3, %4};"
                 :: "l"(gaddr), "f"(v.x), "f"(v.y), "f"(v.z), "f"(v.w) : "memory");
}

__global__ void __launch_bounds__(256)
k_zero(float* __restrict__ out, int n4) {
    int i = blockIdx.x * blockDim.x + threadIdx.x;
    if (i < n4) ((float4*)out)[i] = make_float4(0.f, 0.f, 0.f, 0.f);
}

__global__ void __launch_bounds__(128, 6)
k_hist(const float* __restrict__ x, const float* __restrict__ v,
       const int* __restrict__ batch, int n, float* __restrict__ out) {
    __shared__ u8 H[RR * TT];                    // u8, 4 bins/word/thread
    __shared__ float SX[TILE], SY[TILE], SZ[TILE];
    __shared__ float4 XF[4][32];                 // flush prefix exchange
    __shared__ int seg_end_sh;

    const int t = threadIdx.x;
    const int g = blockIdx.x;
    const u32 hbase = (u32)__cvta_generic_to_shared(H) + ((u32)t << 2);

    const int lo = (int)(((long long)g)     * n / NBLK);
    const int hi = (int)(((long long)g + 1) * n / NBLK);

    const float v0 = v[t];
    const float v1 = v[TT + t];
    const float v2 = v[2 * TT + t];
    const u64 v0p = pack2(v0, v0), v1p = pack2(v1, v1), v2p = pack2(v2, v2);
    const u64 c64p = pack2(64.0f, 64.0f);

    // zero 16KB histogram (conflict-free uint4 stores)
    {
        uint4* a = (uint4*)H;
        for (int i = t; i < (RR * TT) / 16; i += 128)
            a[i] = make_uint4(0u, 0u, 0u, 0u);
    }

    int pos = lo;
    while (pos < hi) {
        if (t == 0) {
            int b = batch[pos];
            seg_end_sh = min(hi, lower_bound_i32(batch, n, b + 1));
        }
        __syncthreads();
        const int seg_end = seg_end_sh;
        const int b = batch[pos];                // uniform broadcast

        for (int base = pos; base < seg_end; base += TILE) {
            const int m = min(TILE, seg_end - base);
            for (int p = t; p < m; p += 128) {
                const float* src = x + (size_t)(base + p) * 3;
                SX[p] = src[0]; SY[p] = src[1]; SZ[p] = src[2];
            }
            __syncthreads();

            int k = 0;
            for (; k + 4 <= m; k += 4) {
                ulonglong2 X = *(const ulonglong2*)(SX + k);
                ulonglong2 Y = *(const ulonglong2*)(SY + k);
                ulonglong2 Z = *(const ulonglong2*)(SZ + k);
                u64 nhA = fma2(Z.x, v2p, fma2(Y.x, v1p, mul2(X.x, v0p)));
                u64 nhB = fma2(Z.y, v2p, fma2(Y.y, v1p, mul2(X.y, v0p)));
                u64 fA  = fma2(nhA, c64p, c64p);
                u64 fB  = fma2(nhB, c64p, c64p);
                float f0, f1, f2, f3;
                unpack2(fA, f0, f1);
                unpack2(fB, f2, f3);
                u32 b0 = bin_clamp(f0), b1 = bin_clamp(f1);
                u32 b2 = bin_clamp(f2), b3 = bin_clamp(f3);
                reds_add(hbase + ((b0 >> 2) << 9), 1u << ((b0 & 3u) << 3));
                reds_add(hbase + ((b1 >> 2) << 9), 1u << ((b1 & 3u) << 3));
                reds_add(hbase + ((b2 >> 2) << 9), 1u << ((b2 & 3u) << 3));
                reds_add(hbase + ((b3 >> 2) << 9), 1u << ((b3 & 3u) << 3));
            }
            for (; k < m; ++k) {
                float nh = fmaf(SZ[k], v2, fmaf(SY[k], v1, __fmul_rn(SX[k], v0)));
                u32 bn = bin_clamp(fmaf(nh, 64.0f, 64.0f));
                reds_add(hbase + ((bn >> 2) << 9), 1u << ((bn & 3u) << 3));
            }
            __syncthreads();                     // drains pending reductions
        }

        // ---- vectorized flush ----
        // warp w owns bins [32w, 32w+32); lane l owns thetas 4l..4l+3.
        {
            const int w = t >> 5, l = t & 31;
            u32* hw = (u32*)H;
            uint4 W[8];
            u32 s0 = 0, s1 = 0, s2 = 0, s3 = 0;
#pragma unroll
            for (int i = 0; i < 8; ++i) {
                uint4* p = (uint4*)(hw + ((8 * w + i) * 128 + 4 * l));
                W[i] = *p;                       // 4 thetas x 4 bins
                *p = make_uint4(0u, 0u, 0u, 0u); // rezero (own read slot)
                s0 = __dp4a(W[i].x, 0x01010101u, s0);   // byte sums
                s1 = __dp4a(W[i].y, 0x01010101u, s1);
                s2 = __dp4a(W[i].z, 0x01010101u, s2);
                s3 = __dp4a(W[i].w, 0x01010101u, s3);
            }
            XF[w][l] = make_float4((float)s0, (float)s1, (float)s2, (float)s3);
            __syncthreads();
            float4 acc = make_float4(0.f, 0.f, 0.f, 0.f);
            for (int w2 = 0; w2 < w; ++w2) {     // warp-uniform trip count
                float4 p = XF[w2][l];
                acc.x += p.x; acc.y += p.y; acc.z += p.z; acc.w += p.w;
            }
            float* dst = out + ((size_t)b * RR + 32 * w) * TT + 4 * l;
#pragma unroll
            for (int i = 0; i < 8; ++i) {
#pragma unroll
                for (int s = 0; s < 4; ++s) {
                    acc.x += (float)((W[i].x >> (8 * s)) & 255u);
                    acc.y += (float)((W[i].y >> (8 * s)) & 255u);
                    acc.z += (float)((W[i].z >> (8 * s)) & 255u);
                    acc.w += (float)((W[i].w >> (8 * s)) & 255u);
                    redg_v4_f32(dst + (size_t)(i * 4 + s) * TT, acc);
                }
            }
        }
        pos = seg_end;
        __syncthreads();                         // XF/H reuse + zero ordering
    }
}

extern "C" void kernel_launch(void* const* d_in, const int* in_sizes, int n_in,
                              void* d_out, int out_size) {
    const float* x     = (const float*)d_in[0];   // [200000, 3]
    const float* v     = (const float*)d_in[1];   // [3, 128]
    const int*   batch = (const int*)d_in[2];     // [200000], sorted
    const int n = in_sizes[2];

    float* out = (float*)d_out;                   // [64, 128, 128]
    const int n4 = out_size / 4;

    k_zero<<<(n4 + 255) / 256, 256>>>(out, n4);
    k_hist<<<NBLK, 128>>>(x, v, batch, n, out);
}